// round 15
// baseline (speedup 1.0000x reference)
#include <cuda_runtime.h>
#include <cuda_bf16.h>
#include <cstdint>

typedef unsigned u32; typedef unsigned long long u64;
typedef __nv_bfloat16 bf16;

// ===================== PTX helpers (portable: sm_80-class only) =====================
__device__ __forceinline__ u32 smem_u32(const void* p){
    u32 a; asm("{ .reg .u64 t; cvta.to.shared.u64 t, %1; cvt.u32.u64 %0, t; }":"=r"(a):"l"(p)); return a;
}
#define CP_ASYNC_CG(dst, src) \
    asm volatile("cp.async.cg.shared.global [%0], [%1], 16;" :: "r"(dst), "l"(src))
#define CP_COMMIT() asm volatile("cp.async.commit_group;" ::: "memory")
#define CP_WAIT(N)  asm volatile("cp.async.wait_group %0;" :: "n"(N) : "memory")

__device__ __forceinline__ void ldm_x4(u32* r, u32 addr){
    asm volatile("ldmatrix.sync.aligned.m8n8.x4.shared.b16 {%0,%1,%2,%3}, [%4];"
        : "=r"(r[0]),"=r"(r[1]),"=r"(r[2]),"=r"(r[3]) : "r"(addr));
}
__device__ __forceinline__ void mma_bf16(float* c, const u32* a, const u32* b){
    asm volatile("mma.sync.aligned.m16n8k16.row.col.f32.bf16.bf16.f32 "
        "{%0,%1,%2,%3}, {%4,%5,%6,%7}, {%8,%9}, {%0,%1,%2,%3};"
        : "+f"(c[0]),"+f"(c[1]),"+f"(c[2]),"+f"(c[3])
        : "r"(a[0]),"r"(a[1]),"r"(a[2]),"r"(a[3]), "r"(b[0]),"r"(b[1]));
}
__device__ __forceinline__ void bf16_split(float v, bf16& h, bf16& l){
    h = __float2bfloat16(v);
    l = __float2bfloat16(v - __bfloat162float(h));
}
__device__ __forceinline__ u32 pack_bf16(bf16 a, bf16 b){
    return (u32)__bfloat16_as_ushort(a) | ((u32)__bfloat16_as_ushort(b) << 16);
}

// float2 arithmetic
__device__ __forceinline__ float2 operator+(float2 a, float2 b){ return make_float2(a.x+b.x, a.y+b.y); }
__device__ __forceinline__ float2 operator-(float2 a, float2 b){ return make_float2(a.x-b.x, a.y-b.y); }
__device__ __forceinline__ float2 operator*(float s, float2 a){ return make_float2(s*a.x, s*a.y); }

// ===================== device scratch =====================
__device__ float g_xT[2ULL*4*4096*1024];        // NHWC fp32: [inp][b][px][ci]
__device__ bf16  g_V1h[2ULL*36*1024*1024];      // [inp][p36][gm1024][ci1024]
__device__ bf16  g_V1l[2ULL*36*1024*1024];
__device__ bf16  g_U1h[36*32*256*32];           // [p][chunk][co][ci32]
__device__ bf16  g_U1l[36*32*256*32];
__device__ float g_M1[2ULL*36*1024*256];        // [inp][p][gm][co]
__device__ float g_buf1[4ULL*4096*512];         // NHWC fp32 concat(cur,key)
__device__ bf16  g_V2h[36ULL*1024*512];
__device__ bf16  g_V2l[36ULL*1024*512];
__device__ bf16  g_U2h[36*16*256*32];
__device__ bf16  g_U2l[36*16*256*32];
__device__ float g_M2[36ULL*1024*256];
__device__ float g_buf2[4ULL*256*4096];         // NCHW conv2 out
__device__ float g_kern[4ULL*81*4096];          // NCHW softmax kernels

// ===================== NCHW -> NHWC fp32 (C=1024) =====================
__global__ void __launch_bounds__(256) nchw_to_nhwc(const float* __restrict__ x, float* __restrict__ xT){
    __shared__ float s[64*65];
    const int tid = threadIdx.x, px0 = blockIdx.x*64, ci0 = blockIdx.y*64, b = blockIdx.z;
    for (int j = tid; j < 4096; j += 256){
        int ci = j>>6, p = j&63;
        s[ci*65+p] = x[((size_t)(b*1024 + ci0+ci))*4096 + px0 + p];
    }
    __syncthreads();
    for (int j = tid; j < 4096; j += 256){
        int p = j>>6, ci = j&63;
        xT[((size_t)b*4096 + px0+p)*1024 + ci0 + ci] = s[ci*65+p];
    }
}

// ===================== F(4,3) weight transform: U = G g G^T (36 pos), bf16 split ====
__global__ void prep_wino_w4(const float* __restrict__ w, bf16* __restrict__ uh, bf16* __restrict__ ul,
                             int CIN, int CH, int total)
{
    int idx = blockIdx.x*256 + threadIdx.x;
    if (idx >= total) return;
    int ci = idx % CIN, co = idx / CIN;
    const float* g = w + ((size_t)co*CIN + ci)*9;
    float q[6][3];
    #pragma unroll
    for (int c = 0; c < 3; c++){
        float g0 = g[c], g1 = g[3+c], g2 = g[6+c];
        q[0][c] = 0.25f*g0;
        q[1][c] = -(g0 + g1 + g2) * (1.f/6.f);
        q[2][c] = (-g0 + g1 - g2) * (1.f/6.f);
        q[3][c] = g0*(1.f/24.f) + g1*(1.f/12.f) + g2*(1.f/6.f);
        q[4][c] = g0*(1.f/24.f) - g1*(1.f/12.f) + g2*(1.f/6.f);
        q[5][c] = g2;
    }
    const int c = ci >> 5, cil = ci & 31;
    #pragma unroll
    for (int r = 0; r < 6; r++){
        float a = q[r][0], b2 = q[r][1], c2 = q[r][2];
        float u[6];
        u[0] = 0.25f*a;
        u[1] = -(a + b2 + c2) * (1.f/6.f);
        u[2] = (-a + b2 - c2) * (1.f/6.f);
        u[3] = a*(1.f/24.f) + b2*(1.f/12.f) + c2*(1.f/6.f);
        u[4] = a*(1.f/24.f) - b2*(1.f/12.f) + c2*(1.f/6.f);
        u[5] = c2;
        #pragma unroll
        for (int cc = 0; cc < 6; cc++){
            int p = r*6 + cc;
            bf16 h, l; bf16_split(u[cc], h, l);
            size_t o = ((size_t)((p*CH + c)*256 + co))*32 + cil;
            uh[o] = h; ul[o] = l;
        }
    }
}

// ===================== F(4,3) input transform: V = B^T d B, bf16 split ==============
template<int CIN>
__global__ void __launch_bounds__(512) wino_in4(
    const float* __restrict__ x, bf16* __restrict__ vh, bf16* __restrict__ vl,
    size_t xstride, size_t vstride)
{
    const int gm = blockIdx.x;
    const int inp = blockIdx.y;
    const int ci = threadIdx.x*2;
    const int b = gm>>8, t = gm&255, ty = t>>4, tx = t&15;
    const float* src = x + inp*xstride + ((size_t)b*4096)*CIN + ci;
    bf16* voh = vh + inp*vstride;
    bf16* vol = vl + inp*vstride;
    const float2 zero = make_float2(0.f, 0.f);

    float2 z[6][6];
    const int py0 = 4*ty - 1;
    #pragma unroll
    for (int c = 0; c < 6; c++){
        const int px = 4*tx - 1 + c;
        const bool okc = (unsigned)px < 64u;
        float2 d[6];
        #pragma unroll
        for (int j = 0; j < 6; j++){
            const int py = py0 + j;
            d[j] = (okc && (unsigned)py < 64u)
                 ? *(const float2*)(src + (size_t)(py*64 + px)*CIN) : zero;
        }
        z[0][c] = 4.f*d[0] - 5.f*d[2] + d[4];
        z[1][c] = -4.f*d[1] - 4.f*d[2] + d[3] + d[4];
        z[2][c] =  4.f*d[1] - 4.f*d[2] - d[3] + d[4];
        z[3][c] = -2.f*d[1] - d[2] + 2.f*d[3] + d[4];
        z[4][c] =  2.f*d[1] - d[2] - 2.f*d[3] + d[4];
        z[5][c] =  4.f*d[1] - 5.f*d[3] + d[5];
    }
    #pragma unroll
    for (int r = 0; r < 6; r++){
        float2 v[6];
        v[0] = 4.f*z[r][0] - 5.f*z[r][2] + z[r][4];
        v[1] = -4.f*z[r][1] - 4.f*z[r][2] + z[r][3] + z[r][4];
        v[2] =  4.f*z[r][1] - 4.f*z[r][2] - z[r][3] + z[r][4];
        v[3] = -2.f*z[r][1] - z[r][2] + 2.f*z[r][3] + z[r][4];
        v[4] =  2.f*z[r][1] - z[r][2] - 2.f*z[r][3] + z[r][4];
        v[5] =  4.f*z[r][1] - 5.f*z[r][3] + z[r][5];
        #pragma unroll
        for (int c = 0; c < 6; c++){
            const int p = r*6 + c;
            const size_t o = ((size_t)p*1024 + gm)*CIN + ci;
            bf16 h0,l0,h1,l1;
            bf16_split(v[c].x, h0, l0); bf16_split(v[c].y, h1, l1);
            *(u32*)(voh + o) = pack_bf16(h0, h1);
            *(u32*)(vol + o) = pack_bf16(l0, l1);
        }
    }
}

// ===================== Winograd-domain GEMM (R10 config: M=128, 512 thr, 3-stage) ==
constexpr int STG = 61440;
constexpr int NSTG = 3;

template <int CIN>
__global__ void __launch_bounds__(512, 1) wino_gemm(
    const bf16* __restrict__ vh, const bf16* __restrict__ vl,
    const bf16* __restrict__ uh, const bf16* __restrict__ ul,
    float* __restrict__ mout)
{
    constexpr int CH = CIN/32;
    constexpr int NITER = CH;
    extern __shared__ char dsm[];

    const int tid = threadIdx.x, wid = tid>>5, lane = tid&31;
    const int m0 = blockIdx.x*128;
    const int p = blockIdx.z;
    const size_t voff = ((size_t)blockIdx.y*36 + p) * 1024 * CIN;
    const size_t moff = ((size_t)blockIdx.y*36 + p) * 1024 * 256;

    const u32 sm0 = smem_u32(dsm);

    const int au = tid >> 1;
    const int arow = au >> 1, ahalf = au & 1;
    const int asub = (tid & 1) * 32;
    const int brow = tid >> 1, bhalf = tid & 1;

    auto stage = [&](int it){
        const int c = it;
        const u32 base = sm0 + (u32)(it % NSTG) * STG;
        {
            const bf16* src = (ahalf ? vl : vh) + voff
                + (size_t)(m0 + arow)*CIN + c*32 + (asub>>1);
            u32 dst = base + ahalf*10240 + arow*80 + asub;
            CP_ASYNC_CG(dst,      src);
            CP_ASYNC_CG(dst + 16, src + 8);
        }
        {
            const bf16* src = (bhalf ? ul : uh)
                + ((size_t)((p*CH + c)*256 + brow)) * 32;
            u32 dst = base + 20480 + bhalf*20480 + brow*80;
            #pragma unroll
            for (int g = 0; g < 4; g++) CP_ASYNC_CG(dst + g*16, src + g*8);
        }
        CP_COMMIT();
    };

    const int wm = wid & 3, wn = wid >> 2;
    const u32 aoff = (u32)((wm*32 + (lane&15))*80 + (lane>>4)*16);
    const u32 boff = (u32)((wn*64 + (lane&7) + ((lane>>4)<<3))*80 + ((lane>>3)&1)*16);

    float acc[2][8][4];
    #pragma unroll
    for (int mf=0; mf<2; mf++)
        #pragma unroll
        for (int nf=0; nf<8; nf++)
            #pragma unroll
            for (int q=0; q<4; q++) acc[mf][nf][q] = 0.f;

    stage(0);
    stage(1);
    for (int it = 0; it < NITER; ++it) {
        CP_WAIT(1);
        __syncthreads();
        if (it + 2 < NITER) stage(it + 2); else CP_COMMIT();

        const u32 sA = sm0 + (u32)(it % NSTG) * STG;
        const u32 sB = sA + 20480;

        #pragma unroll
        for (int s = 0; s < 2; s++) {
            u32 a0[2][4], a1[2][4];
            #pragma unroll
            for (int mf = 0; mf < 2; mf++) {
                ldm_x4(a0[mf], sA + mf*1280 + s*32 + aoff);
                ldm_x4(a1[mf], sA + 10240 + mf*1280 + s*32 + aoff);
            }
            #pragma unroll
            for (int np = 0; np < 2; np++) {
                u32 bh[4][2], bl[4][2];
                #pragma unroll
                for (int q2 = 0; q2 < 2; q2++) {
                    u32 r[4];
                    ldm_x4(r, sB + (np*2+q2)*1280 + s*32 + boff);
                    bh[q2*2][0]=r[0]; bh[q2*2][1]=r[1]; bh[q2*2+1][0]=r[2]; bh[q2*2+1][1]=r[3];
                    ldm_x4(r, sB + 20480 + (np*2+q2)*1280 + s*32 + boff);
                    bl[q2*2][0]=r[0]; bl[q2*2][1]=r[1]; bl[q2*2+1][0]=r[2]; bl[q2*2+1][1]=r[3];
                }
                #pragma unroll
                for (int j = 0; j < 4; j++)
                    #pragma unroll
                    for (int mf = 0; mf < 2; mf++)
                        mma_bf16(acc[mf][np*4+j], a0[mf], bh[j]);
                #pragma unroll
                for (int j = 0; j < 4; j++)
                    #pragma unroll
                    for (int mf = 0; mf < 2; mf++)
                        mma_bf16(acc[mf][np*4+j], a1[mf], bh[j]);
                #pragma unroll
                for (int j = 0; j < 4; j++)
                    #pragma unroll
                    for (int mf = 0; mf < 2; mf++)
                        mma_bf16(acc[mf][np*4+j], a0[mf], bl[j]);
            }
        }
    }

    float* base = mout + moff;
    #pragma unroll
    for (int mf = 0; mf < 2; mf++) {
        #pragma unroll
        for (int nf = 0; nf < 8; nf++) {
            const int co = wn*64 + nf*8 + 2*(lane&3);
            #pragma unroll
            for (int h2 = 0; h2 < 2; h2++) {
                const int m = m0 + wm*32 + mf*16 + (lane>>2) + h2*8;
                float2 v = make_float2(acc[mf][nf][h2*2+0], acc[mf][nf][h2*2+1]);
                *(float2*)(base + (size_t)m*256 + co) = v;
            }
        }
    }
}

// ===================== F(4,3) output transform: Y = A^T M A + bias, relu ============
__global__ void __launch_bounds__(128) wino_out4_nhwc(
    const float* __restrict__ min, const float* __restrict__ bias, float* __restrict__ out)
{
    const int inp = blockIdx.y;
    const int gm = blockIdx.x;
    const int co = threadIdx.x*2;
    const float* base = min + ((size_t)inp*36)*1024*256 + (size_t)gm*256 + co;

    float2 m[36];
    #pragma unroll
    for (int p = 0; p < 36; p++) m[p] = *(const float2*)(base + (size_t)p*1024*256);

    float2 tt[4][6];
    #pragma unroll
    for (int c = 0; c < 6; c++){
        float2 m0=m[c], m1=m[6+c], m2=m[12+c], m3=m[18+c], m4=m[24+c], m5=m[30+c];
        tt[0][c] = m0 + m1 + m2 + m3 + m4;
        tt[1][c] = m1 - m2 + 2.f*m3 - 2.f*m4;
        tt[2][c] = m1 + m2 + 4.f*m3 + 4.f*m4;
        tt[3][c] = m1 - m2 + 8.f*m3 - 8.f*m4 + m5;
    }
    const float2 bv = *(const float2*)(bias + co);
    const int b = gm>>8, t = gm&255, ty = t>>4, tx = t&15;
    #pragma unroll
    for (int r = 0; r < 4; r++){
        float2 y[4];
        y[0] = tt[r][0] + tt[r][1] + tt[r][2] + tt[r][3] + tt[r][4];
        y[1] = tt[r][1] - tt[r][2] + 2.f*tt[r][3] - 2.f*tt[r][4];
        y[2] = tt[r][1] + tt[r][2] + 4.f*tt[r][3] + 4.f*tt[r][4];
        y[3] = tt[r][1] - tt[r][2] + 8.f*tt[r][3] - 8.f*tt[r][4] + tt[r][5];
        #pragma unroll
        for (int c = 0; c < 4; c++){
            float2 v = y[c] + bv;
            v.x = fmaxf(v.x, 0.f); v.y = fmaxf(v.y, 0.f);
            const int px = (4*ty + r)*64 + 4*tx + c;
            *(float2*)(out + ((size_t)(b*4096 + px))*512 + inp*256 + co) = v;
        }
    }
}

__global__ void __launch_bounds__(128) wino_out4_nchw(
    const float* __restrict__ min, const float* __restrict__ bias, float* __restrict__ out)
{
    const int gm = blockIdx.x;
    const int co = threadIdx.x*2;
    const float* base = min + (size_t)gm*256 + co;

    float2 m[36];
    #pragma unroll
    for (int p = 0; p < 36; p++) m[p] = *(const float2*)(base + (size_t)p*1024*256);

    float2 tt[4][6];
    #pragma unroll
    for (int c = 0; c < 6; c++){
        float2 m0=m[c], m1=m[6+c], m2=m[12+c], m3=m[18+c], m4=m[24+c], m5=m[30+c];
        tt[0][c] = m0 + m1 + m2 + m3 + m4;
        tt[1][c] = m1 - m2 + 2.f*m3 - 2.f*m4;
        tt[2][c] = m1 + m2 + 4.f*m3 + 4.f*m4;
        tt[3][c] = m1 - m2 + 8.f*m3 - 8.f*m4 + m5;
    }
    const float2 bv = *(const float2*)(bias + co);
    const int b = gm>>8, t = gm&255, ty = t>>4, tx = t&15;
    #pragma unroll
    for (int r = 0; r < 4; r++){
        float2 y[4];
        y[0] = tt[r][0] + tt[r][1] + tt[r][2] + tt[r][3] + tt[r][4];
        y[1] = tt[r][1] - tt[r][2] + 2.f*tt[r][3] - 2.f*tt[r][4];
        y[2] = tt[r][1] + tt[r][2] + 4.f*tt[r][3] + 4.f*tt[r][4];
        y[3] = tt[r][1] - tt[r][2] + 8.f*tt[r][3] - 8.f*tt[r][4] + tt[r][5];
        #pragma unroll
        for (int c = 0; c < 4; c++){
            float2 v = y[c] + bv;
            const int px = (4*ty + r)*64 + 4*tx + c;
            out[((size_t)(b*256 + co + 0))*4096 + px] = fmaxf(v.x, 0.f);
            out[((size_t)(b*256 + co + 1))*4096 + px] = fmaxf(v.y, 0.f);
        }
    }
}

// ===================== 1x1 conv (256->81) + relu + softmax =====================
__global__ void __launch_bounds__(256) conv1x1_softmax_kernel(
    const float* __restrict__ x2, const float* __restrict__ w3,
    const float* __restrict__ b3, float* __restrict__ kout)
{
    __shared__ float s_w[81*64];
    __shared__ float s_logit[81*64];
    __shared__ float s_m[64], s_r[64];
    const int tid = threadIdx.x, px = tid & 63, grp = tid >> 6;
    const int h = blockIdx.x, b = blockIdx.y;

    float acc[21];
    #pragma unroll
    for (int k = 0; k < 21; k++) { int co = grp + 4*k; acc[k] = (co < 81) ? b3[co] : 0.f; }
    const float* xb = x2 + ((size_t)b*256)*4096 + h*64 + px;

    for (int ci0 = 0; ci0 < 256; ci0 += 64) {
        __syncthreads();
        for (int j = tid; j < 81*64; j += 256) s_w[j] = w3[(j>>6)*256 + ci0 + (j&63)];
        __syncthreads();
        for (int i = 0; i < 64; i++) {
            float xv = __ldg(xb + (size_t)(ci0 + i)*4096);
            #pragma unroll
            for (int k = 0; k < 21; k++) { int co = grp + 4*k; if (co < 81) acc[k] += xv * s_w[co*64 + i]; }
        }
    }
    #pragma unroll
    for (int k = 0; k < 21; k++) { int co = grp + 4*k; if (co < 81) s_logit[co*64 + px] = fmaxf(acc[k], 0.f); }
    __syncthreads();
    if (tid < 64) {
        float m = -1e30f;
        for (int co = 0; co < 81; co++) m = fmaxf(m, s_logit[co*64 + tid]);
        float s = 0.f;
        for (int co = 0; co < 81; co++) s += __expf(s_logit[co*64 + tid] - m);
        s_m[tid] = m; s_r[tid] = 1.f / s;
    }
    __syncthreads();
    float m = s_m[px], rr = s_r[px];
    #pragma unroll
    for (int k = 0; k < 21; k++) {
        int co = grp + 4*k;
        if (co < 81)
            kout[((size_t)(b*81 + co)*4096) + h*64 + px] = __expf(s_logit[co*64 + px] - m) * rr;
    }
}

// ===================== spatially-variant 9x9 conv (v3b: 32 ch/block) ================
// Block 128 threads: tid = cg*16 + pyg*8 + px_x. Thread owns 4 ch x 4 py-rows x 1 px.
// Block covers 8x8 px x 32 ch. grid (8,8,128): z = b*32 + chunk. Dynamic smem 64KB.
constexpr int SVC_DSM = (81*80 + 32*296) * 4;   // 25920 + 37888 B

__global__ void __launch_bounds__(128) svc_kernel(
    const float* __restrict__ feats, const float* __restrict__ kern, float* __restrict__ out)
{
    extern __shared__ float svm[];
    float* k_s = svm;            // 81*80
    float* f_s = svm + 81*80;    // 32*296
    const int tid = threadIdx.x;
    const int px_x = tid & 7;
    const int pyg  = (tid >> 3) & 1;
    const int cg   = tid >> 4;        // 0..7 -> 4 channels each
    const int w0 = blockIdx.x*8, h0 = blockIdx.y*8;
    const int b = blockIdx.z >> 5, cbase = (blockIdx.z & 31) * 32;

    for (int j = tid; j < 81*64; j += 128) {
        int tap = j >> 6, p = j & 63;
        int py = p >> 3, px = p & 7;
        k_s[tap*80 + (py & 3)*16 + (py >> 2)*24 + px] =
            kern[((size_t)(b*81 + tap))*4096 + (size_t)(h0 + py)*64 + w0 + px];
    }
    for (int j = tid; j < 32*256; j += 128) {
        int c = j >> 8, rc = j & 255, r = rc >> 4, cl = rc & 15;
        int gr = h0 + r - 4, gc = w0 + cl - 4;
        float v = 0.f;
        if ((unsigned)gr < 64u && (unsigned)gc < 64u)
            v = feats[((size_t)(b*1024 + cbase + c))*4096 + gr*64 + gc];
        f_s[c*296 + r*18 + cl] = v;
    }
    __syncthreads();

    const float* fp[4];
    #pragma unroll
    for (int e = 0; e < 4; e++) fp[e] = f_s + (cg*4 + e)*296 + px_x;
    const float* kb = k_s + pyg*24 + px_x;

    float acc[4][4] = {};
    #pragma unroll
    for (int rr = 0; rr < 12; rr++) {
        const int rofs = (pyg*4 + rr)*18;
        #pragma unroll
        for (int j = 0; j < 9; j++) {
            float fv[4];
            #pragma unroll
            for (int e = 0; e < 4; e++) fv[e] = fp[e][rofs + j];
            #pragma unroll
            for (int iy = 0; iy < 4; iy++) {
                const int i = rr - iy;
                if (i >= 0 && i <= 8) {
                    const float kv = kb[(i*9 + j)*80 + iy*16];
                    #pragma unroll
                    for (int e = 0; e < 4; e++) acc[e][iy] += fv[e] * kv;
                }
            }
        }
    }

    #pragma unroll
    for (int e = 0; e < 4; e++) {
        #pragma unroll
        for (int iy = 0; iy < 4; iy++) {
            const int py = pyg*4 + iy;
            out[((size_t)(b*1024 + cbase + cg*4 + e))*4096 + (size_t)(h0 + py)*64 + w0 + px_x]
                = acc[e][iy];
        }
    }
}

// ===================== launch =====================
extern "C" void kernel_launch(void* const* d_in, const int* in_sizes, int n_in,
                              void* d_out, int out_size)
{
    (void)in_sizes; (void)n_in; (void)out_size;
    const float* cur  = (const float*)d_in[0];
    const float* keyl = (const float*)d_in[1];
    const float* high = (const float*)d_in[2];
    const float* w1   = (const float*)d_in[3];
    const float* b1   = (const float*)d_in[4];
    const float* w2   = (const float*)d_in[5];
    const float* b2   = (const float*)d_in[6];
    const float* w3   = (const float*)d_in[7];
    const float* b3   = (const float*)d_in[8];
    float* out = (float*)d_out;

    float *xT, *M1, *buf1, *M2, *buf2, *kern;
    bf16 *V1h,*V1l,*U1h,*U1l,*V2h,*V2l,*U2h,*U2l;
    cudaGetSymbolAddress((void**)&xT,  g_xT);
    cudaGetSymbolAddress((void**)&V1h, g_V1h);
    cudaGetSymbolAddress((void**)&V1l, g_V1l);
    cudaGetSymbolAddress((void**)&U1h, g_U1h);
    cudaGetSymbolAddress((void**)&U1l, g_U1l);
    cudaGetSymbolAddress((void**)&M1,  g_M1);
    cudaGetSymbolAddress((void**)&buf1, g_buf1);
    cudaGetSymbolAddress((void**)&V2h, g_V2h);
    cudaGetSymbolAddress((void**)&V2l, g_V2l);
    cudaGetSymbolAddress((void**)&U2h, g_U2h);
    cudaGetSymbolAddress((void**)&U2l, g_U2l);
    cudaGetSymbolAddress((void**)&M2,  g_M2);
    cudaGetSymbolAddress((void**)&buf2, g_buf2);
    cudaGetSymbolAddress((void**)&kern, g_kern);

    const int DSM = NSTG*STG;
    cudaFuncSetAttribute(wino_gemm<1024>, cudaFuncAttributeMaxDynamicSharedMemorySize, DSM);
    cudaFuncSetAttribute(wino_gemm<512>,  cudaFuncAttributeMaxDynamicSharedMemorySize, DSM);
    cudaFuncSetAttribute(svc_kernel, cudaFuncAttributeMaxDynamicSharedMemorySize, SVC_DSM);

    const size_t XSTRIDE = 4ULL*4096*1024;
    const size_t V1STRIDE = 36ULL*1024*1024;

    nchw_to_nhwc<<<dim3(64,16,4), 256>>>(cur,  xT);
    nchw_to_nhwc<<<dim3(64,16,4), 256>>>(keyl, xT + XSTRIDE);
    prep_wino_w4<<<(256*1024+255)/256, 256>>>(w1, U1h, U1l, 1024, 32, 256*1024);
    prep_wino_w4<<<(256*512+255)/256, 256>>>(w2, U2h, U2l, 512, 16, 256*512);

    // conv1
    wino_in4<1024><<<dim3(1024,2), 512>>>(xT, V1h, V1l, XSTRIDE, V1STRIDE);
    wino_gemm<1024><<<dim3(8,2,36), 512, DSM>>>(V1h, V1l, U1h, U1l, M1);
    wino_out4_nhwc<<<dim3(1024,2), 128>>>(M1, b1, buf1);

    // conv2
    wino_in4<512><<<dim3(1024,1), 256>>>(buf1, V2h, V2l, 0, 0);
    wino_gemm<512><<<dim3(8,1,36), 512, DSM>>>(V2h, V2l, U2h, U2l, M2);
    wino_out4_nchw<<<1024, 128>>>(M2, b2, buf2);

    conv1x1_softmax_kernel<<<dim3(64,4), 256>>>(buf2, w3, b3, kern);
    svc_kernel<<<dim3(8,8,128), 128, SVC_DSM>>>(high, kern, out);
}

// round 16
// speedup vs baseline: 1.0547x; 1.0547x over previous
#include <cuda_runtime.h>
#include <cuda_bf16.h>
#include <cstdint>

typedef unsigned u32; typedef unsigned long long u64;
typedef __nv_bfloat16 bf16;

// ===================== PTX helpers (portable: sm_80-class only) =====================
__device__ __forceinline__ u32 smem_u32(const void* p){
    u32 a; asm("{ .reg .u64 t; cvta.to.shared.u64 t, %1; cvt.u32.u64 %0, t; }":"=r"(a):"l"(p)); return a;
}
#define CP_ASYNC_CG(dst, src) \
    asm volatile("cp.async.cg.shared.global [%0], [%1], 16;" :: "r"(dst), "l"(src))
#define CP_COMMIT() asm volatile("cp.async.commit_group;" ::: "memory")
#define CP_WAIT(N)  asm volatile("cp.async.wait_group %0;" :: "n"(N) : "memory")

__device__ __forceinline__ void ldm_x4(u32* r, u32 addr){
    asm volatile("ldmatrix.sync.aligned.m8n8.x4.shared.b16 {%0,%1,%2,%3}, [%4];"
        : "=r"(r[0]),"=r"(r[1]),"=r"(r[2]),"=r"(r[3]) : "r"(addr));
}
__device__ __forceinline__ void mma_bf16(float* c, const u32* a, const u32* b){
    asm volatile("mma.sync.aligned.m16n8k16.row.col.f32.bf16.bf16.f32 "
        "{%0,%1,%2,%3}, {%4,%5,%6,%7}, {%8,%9}, {%0,%1,%2,%3};"
        : "+f"(c[0]),"+f"(c[1]),"+f"(c[2]),"+f"(c[3])
        : "r"(a[0]),"r"(a[1]),"r"(a[2]),"r"(a[3]), "r"(b[0]),"r"(b[1]));
}
__device__ __forceinline__ void bf16_split(float v, bf16& h, bf16& l){
    h = __float2bfloat16(v);
    l = __float2bfloat16(v - __bfloat162float(h));
}
__device__ __forceinline__ u32 pack_bf16(bf16 a, bf16 b){
    return (u32)__bfloat16_as_ushort(a) | ((u32)__bfloat16_as_ushort(b) << 16);
}

// float2 arithmetic
__device__ __forceinline__ float2 operator+(float2 a, float2 b){ return make_float2(a.x+b.x, a.y+b.y); }
__device__ __forceinline__ float2 operator-(float2 a, float2 b){ return make_float2(a.x-b.x, a.y-b.y); }
__device__ __forceinline__ float2 operator*(float s, float2 a){ return make_float2(s*a.x, s*a.y); }

// ===================== device scratch =====================
__device__ float g_xT[2ULL*4*4096*1024];        // NHWC fp32: [inp][b][px][ci]
__device__ bf16  g_V1h[2ULL*36*1024*1024];      // [inp][p36][gm1024][ci1024]
__device__ bf16  g_V1l[2ULL*36*1024*1024];
__device__ bf16  g_U1h[36*32*256*32];           // [p][chunk][co][ci32]
__device__ bf16  g_U1l[36*32*256*32];
__device__ float g_M1[2ULL*36*1024*256];        // [inp][p][gm][co]
__device__ float g_buf1[4ULL*4096*512];         // NHWC fp32 concat(cur,key)
__device__ bf16  g_V2h[36ULL*1024*512];
__device__ bf16  g_V2l[36ULL*1024*512];
__device__ bf16  g_U2h[36*16*256*32];
__device__ bf16  g_U2l[36*16*256*32];
__device__ float g_M2[36ULL*1024*256];
__device__ float g_buf2[4ULL*256*4096];         // NCHW conv2 out
__device__ float g_kern[4ULL*81*4096];          // NCHW softmax kernels

// ===================== NCHW -> NHWC fp32 (C=1024), both inputs in one launch ========
__global__ void __launch_bounds__(256) nchw_to_nhwc2(
    const float* __restrict__ x0, const float* __restrict__ x1, float* __restrict__ xT,
    size_t xTstride)
{
    __shared__ float s[64*65];
    const int tid = threadIdx.x, px0 = blockIdx.x*64, ci0 = blockIdx.y*64;
    const int b = blockIdx.z & 3, inp = blockIdx.z >> 2;
    const float* x = inp ? x1 : x0;
    float* dst = xT + inp*xTstride;
    for (int j = tid; j < 4096; j += 256){
        int ci = j>>6, p = j&63;
        s[ci*65+p] = x[((size_t)(b*1024 + ci0+ci))*4096 + px0 + p];
    }
    __syncthreads();
    for (int j = tid; j < 4096; j += 256){
        int p = j>>6, ci = j&63;
        dst[((size_t)b*4096 + px0+p)*1024 + ci0 + ci] = s[ci*65+p];
    }
}

// ===================== F(4,3) weight transform: U = G g G^T (36 pos), bf16 split ====
__global__ void prep_wino_w4(const float* __restrict__ w, bf16* __restrict__ uh, bf16* __restrict__ ul,
                             int CIN, int CH, int total)
{
    int idx = blockIdx.x*256 + threadIdx.x;
    if (idx >= total) return;
    int ci = idx % CIN, co = idx / CIN;
    const float* g = w + ((size_t)co*CIN + ci)*9;
    float q[6][3];
    #pragma unroll
    for (int c = 0; c < 3; c++){
        float g0 = g[c], g1 = g[3+c], g2 = g[6+c];
        q[0][c] = 0.25f*g0;
        q[1][c] = -(g0 + g1 + g2) * (1.f/6.f);
        q[2][c] = (-g0 + g1 - g2) * (1.f/6.f);
        q[3][c] = g0*(1.f/24.f) + g1*(1.f/12.f) + g2*(1.f/6.f);
        q[4][c] = g0*(1.f/24.f) - g1*(1.f/12.f) + g2*(1.f/6.f);
        q[5][c] = g2;
    }
    const int c = ci >> 5, cil = ci & 31;
    #pragma unroll
    for (int r = 0; r < 6; r++){
        float a = q[r][0], b2 = q[r][1], c2 = q[r][2];
        float u[6];
        u[0] = 0.25f*a;
        u[1] = -(a + b2 + c2) * (1.f/6.f);
        u[2] = (-a + b2 - c2) * (1.f/6.f);
        u[3] = a*(1.f/24.f) + b2*(1.f/12.f) + c2*(1.f/6.f);
        u[4] = a*(1.f/24.f) - b2*(1.f/12.f) + c2*(1.f/6.f);
        u[5] = c2;
        #pragma unroll
        for (int cc = 0; cc < 6; cc++){
            int p = r*6 + cc;
            bf16 h, l; bf16_split(u[cc], h, l);
            size_t o = ((size_t)((p*CH + c)*256 + co))*32 + cil;
            uh[o] = h; ul[o] = l;
        }
    }
}

// ===================== F(4,3) input transform: V = B^T d B, bf16 split ==============
template<int CIN>
__global__ void __launch_bounds__(512) wino_in4(
    const float* __restrict__ x, bf16* __restrict__ vh, bf16* __restrict__ vl,
    size_t xstride, size_t vstride)
{
    const int gm = blockIdx.x;
    const int inp = blockIdx.y;
    const int ci = threadIdx.x*2;
    const int b = gm>>8, t = gm&255, ty = t>>4, tx = t&15;
    const float* src = x + inp*xstride + ((size_t)b*4096)*CIN + ci;
    bf16* voh = vh + inp*vstride;
    bf16* vol = vl + inp*vstride;
    const float2 zero = make_float2(0.f, 0.f);

    float2 z[6][6];
    const int py0 = 4*ty - 1;
    #pragma unroll
    for (int c = 0; c < 6; c++){
        const int px = 4*tx - 1 + c;
        const bool okc = (unsigned)px < 64u;
        float2 d[6];
        #pragma unroll
        for (int j = 0; j < 6; j++){
            const int py = py0 + j;
            d[j] = (okc && (unsigned)py < 64u)
                 ? *(const float2*)(src + (size_t)(py*64 + px)*CIN) : zero;
        }
        z[0][c] = 4.f*d[0] - 5.f*d[2] + d[4];
        z[1][c] = -4.f*d[1] - 4.f*d[2] + d[3] + d[4];
        z[2][c] =  4.f*d[1] - 4.f*d[2] - d[3] + d[4];
        z[3][c] = -2.f*d[1] - d[2] + 2.f*d[3] + d[4];
        z[4][c] =  2.f*d[1] - d[2] - 2.f*d[3] + d[4];
        z[5][c] =  4.f*d[1] - 5.f*d[3] + d[5];
    }
    #pragma unroll
    for (int r = 0; r < 6; r++){
        float2 v[6];
        v[0] = 4.f*z[r][0] - 5.f*z[r][2] + z[r][4];
        v[1] = -4.f*z[r][1] - 4.f*z[r][2] + z[r][3] + z[r][4];
        v[2] =  4.f*z[r][1] - 4.f*z[r][2] - z[r][3] + z[r][4];
        v[3] = -2.f*z[r][1] - z[r][2] + 2.f*z[r][3] + z[r][4];
        v[4] =  2.f*z[r][1] - z[r][2] - 2.f*z[r][3] + z[r][4];
        v[5] =  4.f*z[r][1] - 5.f*z[r][3] + z[r][5];
        #pragma unroll
        for (int c = 0; c < 6; c++){
            const int p = r*6 + c;
            const size_t o = ((size_t)p*1024 + gm)*CIN + ci;
            bf16 h0,l0,h1,l1;
            bf16_split(v[c].x, h0, l0); bf16_split(v[c].y, h1, l1);
            *(u32*)(voh + o) = pack_bf16(h0, h1);
            *(u32*)(vol + o) = pack_bf16(l0, l1);
        }
    }
}

// ===================== Winograd-domain GEMM (R10 config: M=128, 512 thr, 3-stage) ==
constexpr int STG = 61440;
constexpr int NSTG = 3;

template <int CIN>
__global__ void __launch_bounds__(512, 1) wino_gemm(
    const bf16* __restrict__ vh, const bf16* __restrict__ vl,
    const bf16* __restrict__ uh, const bf16* __restrict__ ul,
    float* __restrict__ mout)
{
    constexpr int CH = CIN/32;
    constexpr int NITER = CH;
    extern __shared__ char dsm[];

    const int tid = threadIdx.x, wid = tid>>5, lane = tid&31;
    const int m0 = blockIdx.x*128;
    const int p = blockIdx.z;
    const size_t voff = ((size_t)blockIdx.y*36 + p) * 1024 * CIN;
    const size_t moff = ((size_t)blockIdx.y*36 + p) * 1024 * 256;

    const u32 sm0 = smem_u32(dsm);

    const int au = tid >> 1;
    const int arow = au >> 1, ahalf = au & 1;
    const int asub = (tid & 1) * 32;
    const int brow = tid >> 1, bhalf = tid & 1;

    auto stage = [&](int it){
        const int c = it;
        const u32 base = sm0 + (u32)(it % NSTG) * STG;
        {
            const bf16* src = (ahalf ? vl : vh) + voff
                + (size_t)(m0 + arow)*CIN + c*32 + (asub>>1);
            u32 dst = base + ahalf*10240 + arow*80 + asub;
            CP_ASYNC_CG(dst,      src);
            CP_ASYNC_CG(dst + 16, src + 8);
        }
        {
            const bf16* src = (bhalf ? ul : uh)
                + ((size_t)((p*CH + c)*256 + brow)) * 32;
            u32 dst = base + 20480 + bhalf*20480 + brow*80;
            #pragma unroll
            for (int g = 0; g < 4; g++) CP_ASYNC_CG(dst + g*16, src + g*8);
        }
        CP_COMMIT();
    };

    const int wm = wid & 3, wn = wid >> 2;
    const u32 aoff = (u32)((wm*32 + (lane&15))*80 + (lane>>4)*16);
    const u32 boff = (u32)((wn*64 + (lane&7) + ((lane>>4)<<3))*80 + ((lane>>3)&1)*16);

    float acc[2][8][4];
    #pragma unroll
    for (int mf=0; mf<2; mf++)
        #pragma unroll
        for (int nf=0; nf<8; nf++)
            #pragma unroll
            for (int q=0; q<4; q++) acc[mf][nf][q] = 0.f;

    stage(0);
    stage(1);
    for (int it = 0; it < NITER; ++it) {
        CP_WAIT(1);
        __syncthreads();
        if (it + 2 < NITER) stage(it + 2); else CP_COMMIT();

        const u32 sA = sm0 + (u32)(it % NSTG) * STG;
        const u32 sB = sA + 20480;

        #pragma unroll
        for (int s = 0; s < 2; s++) {
            u32 a0[2][4], a1[2][4];
            #pragma unroll
            for (int mf = 0; mf < 2; mf++) {
                ldm_x4(a0[mf], sA + mf*1280 + s*32 + aoff);
                ldm_x4(a1[mf], sA + 10240 + mf*1280 + s*32 + aoff);
            }
            #pragma unroll
            for (int np = 0; np < 2; np++) {
                u32 bh[4][2], bl[4][2];
                #pragma unroll
                for (int q2 = 0; q2 < 2; q2++) {
                    u32 r[4];
                    ldm_x4(r, sB + (np*2+q2)*1280 + s*32 + boff);
                    bh[q2*2][0]=r[0]; bh[q2*2][1]=r[1]; bh[q2*2+1][0]=r[2]; bh[q2*2+1][1]=r[3];
                    ldm_x4(r, sB + 20480 + (np*2+q2)*1280 + s*32 + boff);
                    bl[q2*2][0]=r[0]; bl[q2*2][1]=r[1]; bl[q2*2+1][0]=r[2]; bl[q2*2+1][1]=r[3];
                }
                #pragma unroll
                for (int j = 0; j < 4; j++)
                    #pragma unroll
                    for (int mf = 0; mf < 2; mf++)
                        mma_bf16(acc[mf][np*4+j], a0[mf], bh[j]);
                #pragma unroll
                for (int j = 0; j < 4; j++)
                    #pragma unroll
                    for (int mf = 0; mf < 2; mf++)
                        mma_bf16(acc[mf][np*4+j], a1[mf], bh[j]);
                #pragma unroll
                for (int j = 0; j < 4; j++)
                    #pragma unroll
                    for (int mf = 0; mf < 2; mf++)
                        mma_bf16(acc[mf][np*4+j], a0[mf], bl[j]);
            }
        }
    }

    float* base = mout + moff;
    #pragma unroll
    for (int mf = 0; mf < 2; mf++) {
        #pragma unroll
        for (int nf = 0; nf < 8; nf++) {
            const int co = wn*64 + nf*8 + 2*(lane&3);
            #pragma unroll
            for (int h2 = 0; h2 < 2; h2++) {
                const int m = m0 + wm*32 + mf*16 + (lane>>2) + h2*8;
                float2 v = make_float2(acc[mf][nf][h2*2+0], acc[mf][nf][h2*2+1]);
                *(float2*)(base + (size_t)m*256 + co) = v;
            }
        }
    }
}

// ===================== F(4,3) output transform: Y = A^T M A + bias, relu ============
__global__ void __launch_bounds__(128) wino_out4_nhwc(
    const float* __restrict__ min, const float* __restrict__ bias, float* __restrict__ out)
{
    const int inp = blockIdx.y;
    const int gm = blockIdx.x;
    const int co = threadIdx.x*2;
    const float* base = min + ((size_t)inp*36)*1024*256 + (size_t)gm*256 + co;

    float2 m[36];
    #pragma unroll
    for (int p = 0; p < 36; p++) m[p] = *(const float2*)(base + (size_t)p*1024*256);

    float2 tt[4][6];
    #pragma unroll
    for (int c = 0; c < 6; c++){
        float2 m0=m[c], m1=m[6+c], m2=m[12+c], m3=m[18+c], m4=m[24+c], m5=m[30+c];
        tt[0][c] = m0 + m1 + m2 + m3 + m4;
        tt[1][c] = m1 - m2 + 2.f*m3 - 2.f*m4;
        tt[2][c] = m1 + m2 + 4.f*m3 + 4.f*m4;
        tt[3][c] = m1 - m2 + 8.f*m3 - 8.f*m4 + m5;
    }
    const float2 bv = *(const float2*)(bias + co);
    const int b = gm>>8, t = gm&255, ty = t>>4, tx = t&15;
    #pragma unroll
    for (int r = 0; r < 4; r++){
        float2 y[4];
        y[0] = tt[r][0] + tt[r][1] + tt[r][2] + tt[r][3] + tt[r][4];
        y[1] = tt[r][1] - tt[r][2] + 2.f*tt[r][3] - 2.f*tt[r][4];
        y[2] = tt[r][1] + tt[r][2] + 4.f*tt[r][3] + 4.f*tt[r][4];
        y[3] = tt[r][1] - tt[r][2] + 8.f*tt[r][3] - 8.f*tt[r][4] + tt[r][5];
        #pragma unroll
        for (int c = 0; c < 4; c++){
            float2 v = y[c] + bv;
            v.x = fmaxf(v.x, 0.f); v.y = fmaxf(v.y, 0.f);
            const int px = (4*ty + r)*64 + 4*tx + c;
            *(float2*)(out + ((size_t)(b*4096 + px))*512 + inp*256 + co) = v;
        }
    }
}

__global__ void __launch_bounds__(128) wino_out4_nchw(
    const float* __restrict__ min, const float* __restrict__ bias, float* __restrict__ out)
{
    const int gm = blockIdx.x;
    const int co = threadIdx.x*2;
    const float* base = min + (size_t)gm*256 + co;

    float2 m[36];
    #pragma unroll
    for (int p = 0; p < 36; p++) m[p] = *(const float2*)(base + (size_t)p*1024*256);

    float2 tt[4][6];
    #pragma unroll
    for (int c = 0; c < 6; c++){
        float2 m0=m[c], m1=m[6+c], m2=m[12+c], m3=m[18+c], m4=m[24+c], m5=m[30+c];
        tt[0][c] = m0 + m1 + m2 + m3 + m4;
        tt[1][c] = m1 - m2 + 2.f*m3 - 2.f*m4;
        tt[2][c] = m1 + m2 + 4.f*m3 + 4.f*m4;
        tt[3][c] = m1 - m2 + 8.f*m3 - 8.f*m4 + m5;
    }
    const float2 bv = *(const float2*)(bias + co);
    const int b = gm>>8, t = gm&255, ty = t>>4, tx = t&15;
    #pragma unroll
    for (int r = 0; r < 4; r++){
        float2 y[4];
        y[0] = tt[r][0] + tt[r][1] + tt[r][2] + tt[r][3] + tt[r][4];
        y[1] = tt[r][1] - tt[r][2] + 2.f*tt[r][3] - 2.f*tt[r][4];
        y[2] = tt[r][1] + tt[r][2] + 4.f*tt[r][3] + 4.f*tt[r][4];
        y[3] = tt[r][1] - tt[r][2] + 8.f*tt[r][3] - 8.f*tt[r][4] + tt[r][5];
        #pragma unroll
        for (int c = 0; c < 4; c++){
            float2 v = y[c] + bv;
            const int px = (4*ty + r)*64 + 4*tx + c;
            out[((size_t)(b*256 + co + 0))*4096 + px] = fmaxf(v.x, 0.f);
            out[((size_t)(b*256 + co + 1))*4096 + px] = fmaxf(v.y, 0.f);
        }
    }
}

// ===================== 1x1 conv (256->81) + relu + softmax =====================
__global__ void __launch_bounds__(256) conv1x1_softmax_kernel(
    const float* __restrict__ x2, const float* __restrict__ w3,
    const float* __restrict__ b3, float* __restrict__ kout)
{
    __shared__ float s_w[81*64];
    __shared__ float s_logit[81*64];
    __shared__ float s_m[64], s_r[64];
    const int tid = threadIdx.x, px = tid & 63, grp = tid >> 6;
    const int h = blockIdx.x, b = blockIdx.y;

    float acc[21];
    #pragma unroll
    for (int k = 0; k < 21; k++) { int co = grp + 4*k; acc[k] = (co < 81) ? b3[co] : 0.f; }
    const float* xb = x2 + ((size_t)b*256)*4096 + h*64 + px;

    for (int ci0 = 0; ci0 < 256; ci0 += 64) {
        __syncthreads();
        for (int j = tid; j < 81*64; j += 256) s_w[j] = w3[(j>>6)*256 + ci0 + (j&63)];
        __syncthreads();
        for (int i = 0; i < 64; i++) {
            float xv = __ldg(xb + (size_t)(ci0 + i)*4096);
            #pragma unroll
            for (int k = 0; k < 21; k++) { int co = grp + 4*k; if (co < 81) acc[k] += xv * s_w[co*64 + i]; }
        }
    }
    #pragma unroll
    for (int k = 0; k < 21; k++) { int co = grp + 4*k; if (co < 81) s_logit[co*64 + px] = fmaxf(acc[k], 0.f); }
    __syncthreads();
    if (tid < 64) {
        float m = -1e30f;
        for (int co = 0; co < 81; co++) m = fmaxf(m, s_logit[co*64 + tid]);
        float s = 0.f;
        for (int co = 0; co < 81; co++) s += __expf(s_logit[co*64 + tid] - m);
        s_m[tid] = m; s_r[tid] = 1.f / s;
    }
    __syncthreads();
    float m = s_m[px], rr = s_r[px];
    #pragma unroll
    for (int k = 0; k < 21; k++) {
        int co = grp + 4*k;
        if (co < 81)
            kout[((size_t)(b*81 + co)*4096) + h*64 + px] = __expf(s_logit[co*64 + px] - m) * rr;
    }
}

// ===================== spatially-variant 9x9 conv (v3: vertical output reuse) =======
__global__ void __launch_bounds__(128) svc_kernel(
    const float* __restrict__ feats, const float* __restrict__ kern, float* __restrict__ out)
{
    __shared__ float k_s[81*80];      // 25920 B
    __shared__ float f_s[16*296];     // 18944 B
    const int tid = threadIdx.x;
    const int px_x = tid & 7;
    const int pyg  = (tid >> 3) & 1;
    const int cg   = tid >> 4;        // 0..7 -> 2 channels each
    const int w0 = blockIdx.x*8, h0 = blockIdx.y*8;
    const int b = blockIdx.z >> 6, cbase = (blockIdx.z & 63) * 16;

    for (int j = tid; j < 81*64; j += 128) {
        int tap = j >> 6, p = j & 63;
        int py = p >> 3, px = p & 7;
        k_s[tap*80 + (py & 3)*16 + (py >> 2)*24 + px] =
            kern[((size_t)(b*81 + tap))*4096 + (size_t)(h0 + py)*64 + w0 + px];
    }
    for (int j = tid; j < 16*256; j += 128) {
        int c = j >> 8, rc = j & 255, r = rc >> 4, cl = rc & 15;
        int gr = h0 + r - 4, gc = w0 + cl - 4;
        float v = 0.f;
        if ((unsigned)gr < 64u && (unsigned)gc < 64u)
            v = feats[((size_t)(b*1024 + cbase + c))*4096 + gr*64 + gc];
        f_s[c*296 + r*18 + cl] = v;
    }
    __syncthreads();

    const float* f0 = f_s + (cg*2 + 0)*296 + px_x;
    const float* f1 = f_s + (cg*2 + 1)*296 + px_x;
    const float* kb = k_s + pyg*24 + px_x;

    float acc[2][4] = {};
    #pragma unroll
    for (int rr = 0; rr < 12; rr++) {
        const int rofs = (pyg*4 + rr)*18;
        #pragma unroll
        for (int j = 0; j < 9; j++) {
            const float fv0 = f0[rofs + j];
            const float fv1 = f1[rofs + j];
            #pragma unroll
            for (int iy = 0; iy < 4; iy++) {
                const int i = rr - iy;
                if (i >= 0 && i <= 8) {
                    const float kv = kb[(i*9 + j)*80 + iy*16];
                    acc[0][iy] += fv0 * kv;
                    acc[1][iy] += fv1 * kv;
                }
            }
        }
    }

    #pragma unroll
    for (int e = 0; e < 2; e++) {
        #pragma unroll
        for (int iy = 0; iy < 4; iy++) {
            const int py = pyg*4 + iy;
            out[((size_t)(b*1024 + cbase + cg*2 + e))*4096 + (size_t)(h0 + py)*64 + w0 + px_x]
                = acc[e][iy];
        }
    }
}

// ===================== launch =====================
extern "C" void kernel_launch(void* const* d_in, const int* in_sizes, int n_in,
                              void* d_out, int out_size)
{
    (void)in_sizes; (void)n_in; (void)out_size;
    const float* cur  = (const float*)d_in[0];
    const float* keyl = (const float*)d_in[1];
    const float* high = (const float*)d_in[2];
    const float* w1   = (const float*)d_in[3];
    const float* b1   = (const float*)d_in[4];
    const float* w2   = (const float*)d_in[5];
    const float* b2   = (const float*)d_in[6];
    const float* w3   = (const float*)d_in[7];
    const float* b3   = (const float*)d_in[8];
    float* out = (float*)d_out;

    float *xT, *M1, *buf1, *M2, *buf2, *kern;
    bf16 *V1h,*V1l,*U1h,*U1l,*V2h,*V2l,*U2h,*U2l;
    cudaGetSymbolAddress((void**)&xT,  g_xT);
    cudaGetSymbolAddress((void**)&V1h, g_V1h);
    cudaGetSymbolAddress((void**)&V1l, g_V1l);
    cudaGetSymbolAddress((void**)&U1h, g_U1h);
    cudaGetSymbolAddress((void**)&U1l, g_U1l);
    cudaGetSymbolAddress((void**)&M1,  g_M1);
    cudaGetSymbolAddress((void**)&buf1, g_buf1);
    cudaGetSymbolAddress((void**)&V2h, g_V2h);
    cudaGetSymbolAddress((void**)&V2l, g_V2l);
    cudaGetSymbolAddress((void**)&U2h, g_U2h);
    cudaGetSymbolAddress((void**)&U2l, g_U2l);
    cudaGetSymbolAddress((void**)&M2,  g_M2);
    cudaGetSymbolAddress((void**)&buf2, g_buf2);
    cudaGetSymbolAddress((void**)&kern, g_kern);

    const int DSM = NSTG*STG;
    cudaFuncSetAttribute(wino_gemm<1024>, cudaFuncAttributeMaxDynamicSharedMemorySize, DSM);
    cudaFuncSetAttribute(wino_gemm<512>,  cudaFuncAttributeMaxDynamicSharedMemorySize, DSM);

    const size_t XSTRIDE = 4ULL*4096*1024;
    const size_t V1STRIDE = 36ULL*1024*1024;

    nchw_to_nhwc2<<<dim3(64,16,8), 256>>>(cur, keyl, xT, XSTRIDE);
    prep_wino_w4<<<(256*1024+255)/256, 256>>>(w1, U1h, U1l, 1024, 32, 256*1024);
    prep_wino_w4<<<(256*512+255)/256, 256>>>(w2, U2h, U2l, 512, 16, 256*512);

    // conv1
    wino_in4<1024><<<dim3(1024,2), 512>>>(xT, V1h, V1l, XSTRIDE, V1STRIDE);
    wino_gemm<1024><<<dim3(8,2,36), 512, DSM>>>(V1h, V1l, U1h, U1l, M1);
    wino_out4_nhwc<<<dim3(1024,2), 128>>>(M1, b1, buf1);

    // conv2
    wino_in4<512><<<dim3(1024,1), 256>>>(buf1, V2h, V2l, 0, 0);
    wino_gemm<512><<<dim3(8,1,36), 512, DSM>>>(V2h, V2l, U2h, U2l, M2);
    wino_out4_nchw<<<1024, 128>>>(M2, b2, buf2);

    conv1x1_softmax_kernel<<<dim3(64,4), 256>>>(buf2, w3, b3, kern);
    svc_kernel<<<dim3(8,8,256), 128>>>(high, kern, out);
}